// round 1
// baseline (speedup 1.0000x reference)
#include <cuda_runtime.h>
#include <cstdint>

#define DFEAT 256
#define NCOLS 512
#define MAXN  100000

// Scratch (no cudaMalloc allowed): P = [u | v] per node, Wcat = rearranged W1.
__device__ float g_P[(size_t)MAXN * NCOLS];   // 204.8 MB
__device__ float g_W[DFEAT * NCOLS];          // 512 KB, tf32-rounded

__device__ __forceinline__ uint32_t f2tf32(float x) {
    uint32_t r;
    asm("cvt.rna.tf32.f32 %0, %1;" : "=r"(r) : "f"(x));
    return r;
}

// Build Wcat[k][j] = W1[k][j] (j<256) | W1[256+k][j-256], tf32-rounded.
__global__ void prep_w(const float* __restrict__ W1) {
    int idx = blockIdx.x * blockDim.x + threadIdx.x;
    if (idx >= DFEAT * NCOLS) return;
    int k = idx >> 9;          // /512
    int j = idx & 511;
    float w = (j < DFEAT) ? W1[k * DFEAT + j]
                          : W1[(DFEAT + k) * DFEAT + (j - DFEAT)];
    g_W[idx] = __uint_as_float(f2tf32(w));
}

// ---------------- tf32 tensor-core GEMM: P[M,512] = h[M,256] @ Wcat ----------
#define BM 128
#define BN 128
#define BK 32
#define ASTR 36    // 36 mod 32 = 4  -> conflict-free A-fragment LDS
#define BSTR 136   // 136 mod 32 = 8 -> conflict-free B-fragment LDS

__global__ __launch_bounds__(256, 1) void gemm_tf32(const float* __restrict__ h, int M) {
    __shared__ float As[BM * ASTR];   // 18.0 KB
    __shared__ float Bs[BK * BSTR];   // 17.0 KB
    int tid  = threadIdx.x;
    int lane = tid & 31, warp = tid >> 5;
    int wm = (warp >> 2) * 64;        // warp grid 2 (m) x 4 (n), warp tile 64x32
    int wn = (warp & 3) * 32;
    int g  = lane >> 2, tg = lane & 3;
    int rowBase = blockIdx.y * BM;    // y = M tile (x-fastest launch => A reuse in L2)
    int nBase   = blockIdx.x * BN;    // x = N tile (4 of them)

    float c[4][4][4];
    #pragma unroll
    for (int i = 0; i < 4; i++)
        #pragma unroll
        for (int j = 0; j < 4; j++)
            #pragma unroll
            for (int q = 0; q < 4; q++) c[i][j][q] = 0.f;

    for (int k0 = 0; k0 < DFEAT; k0 += BK) {
        // ---- load A tile 128x32 (tf32-round on the way in) ----
        #pragma unroll
        for (int i = 0; i < 4; i++) {
            int idx = tid + 256 * i;       // 0..1023 float4 slots
            int r   = idx >> 3;
            int c4  = (idx & 7) << 2;
            float4 v = make_float4(0.f, 0.f, 0.f, 0.f);
            int grow = rowBase + r;
            if (grow < M) v = *(const float4*)(h + (size_t)grow * DFEAT + k0 + c4);
            float* dst = As + r * ASTR + c4;
            dst[0] = __uint_as_float(f2tf32(v.x));
            dst[1] = __uint_as_float(f2tf32(v.y));
            dst[2] = __uint_as_float(f2tf32(v.z));
            dst[3] = __uint_as_float(f2tf32(v.w));
        }
        // ---- load B tile 32x128 (already tf32-rounded) ----
        #pragma unroll
        for (int i = 0; i < 4; i++) {
            int idx = tid + 256 * i;       // 0..1023 float4 slots
            int r   = idx >> 5;
            int c4  = (idx & 31) << 2;
            float4 v = *(const float4*)(g_W + (size_t)(k0 + r) * NCOLS + nBase + c4);
            float* dst = Bs + r * BSTR + c4;
            dst[0] = v.x; dst[1] = v.y; dst[2] = v.z; dst[3] = v.w;
        }
        __syncthreads();

        #pragma unroll
        for (int kk = 0; kk < BK; kk += 8) {
            // A fragments (m16n8k8 tf32): a0 (g,tg) a1 (g+8,tg) a2 (g,tg+4) a3 (g+8,tg+4)
            uint32_t a[4][4];
            #pragma unroll
            for (int mt = 0; mt < 4; mt++) {
                const float* ap = As + (wm + mt * 16) * ASTR + kk;
                a[mt][0] = __float_as_uint(ap[g * ASTR + tg]);
                a[mt][1] = __float_as_uint(ap[(g + 8) * ASTR + tg]);
                a[mt][2] = __float_as_uint(ap[g * ASTR + tg + 4]);
                a[mt][3] = __float_as_uint(ap[(g + 8) * ASTR + tg + 4]);
            }
            // B fragments: b0 (row=tg, col=g), b1 (row=tg+4, col=g)
            uint32_t b[4][2];
            #pragma unroll
            for (int nt = 0; nt < 4; nt++) {
                const float* bp = Bs + kk * BSTR + wn + nt * 8 + g;
                b[nt][0] = __float_as_uint(bp[tg * BSTR]);
                b[nt][1] = __float_as_uint(bp[(tg + 4) * BSTR]);
            }
            #pragma unroll
            for (int mt = 0; mt < 4; mt++)
                #pragma unroll
                for (int nt = 0; nt < 4; nt++) {
                    asm volatile(
                        "mma.sync.aligned.m16n8k8.row.col.f32.tf32.tf32.f32 "
                        "{%0,%1,%2,%3}, {%4,%5,%6,%7}, {%8,%9}, {%0,%1,%2,%3};"
                        : "+f"(c[mt][nt][0]), "+f"(c[mt][nt][1]),
                          "+f"(c[mt][nt][2]), "+f"(c[mt][nt][3])
                        : "r"(a[mt][0]), "r"(a[mt][1]), "r"(a[mt][2]), "r"(a[mt][3]),
                          "r"(b[nt][0]), "r"(b[nt][1]));
                }
        }
        __syncthreads();
    }

    // ---- epilogue: C layout c0 (g,2tg) c1 (g,2tg+1) c2 (g+8,2tg) c3 (g+8,2tg+1)
    #pragma unroll
    for (int mt = 0; mt < 4; mt++) {
        int row0 = rowBase + wm + mt * 16 + g;
        #pragma unroll
        for (int nt = 0; nt < 4; nt++) {
            int col = nBase + wn + nt * 8 + 2 * tg;
            if (row0 < M)
                *(float2*)(g_P + (size_t)row0 * NCOLS + col) =
                    make_float2(c[mt][nt][0], c[mt][nt][1]);
            if (row0 + 8 < M)
                *(float2*)(g_P + (size_t)(row0 + 8) * NCOLS + col) =
                    make_float2(c[mt][nt][2], c[mt][nt][3]);
        }
    }
}

// ---------------- edge pass: warp per edge, gather u[src]+v[dst] -------------
__global__ __launch_bounds__(256) void edge_mlp(
        const int* __restrict__ src, const int* __restrict__ dst,
        const float* __restrict__ b1, const float* __restrict__ W2,
        const float* __restrict__ b2, float* __restrict__ out, int E) {
    __shared__ float4 sb1[DFEAT / 4];
    __shared__ float4 sw2[DFEAT / 4];
    int tid = threadIdx.x;
    if (tid < DFEAT / 4) {
        sb1[tid] = ((const float4*)b1)[tid];
        sw2[tid] = ((const float4*)W2)[tid];
    }
    __syncthreads();

    int e = blockIdx.x * 8 + (tid >> 5);
    if (e >= E) return;
    int lane = tid & 31;
    int s = src[e], d = dst[e];
    const float4* up = (const float4*)(g_P + (size_t)s * NCOLS);
    const float4* vp = (const float4*)(g_P + (size_t)d * NCOLS + DFEAT);

    float acc = 0.f;
    #pragma unroll
    for (int i = 0; i < 2; i++) {
        int j4 = lane + 32 * i;                 // coalesced 512B per request
        float4 u = up[j4], v = vp[j4], bb = sb1[j4], ww = sw2[j4];
        float t;
        t = u.x + v.x + bb.x; if (t > 0.f) acc += t * ww.x;
        t = u.y + v.y + bb.y; if (t > 0.f) acc += t * ww.y;
        t = u.z + v.z + bb.z; if (t > 0.f) acc += t * ww.z;
        t = u.w + v.w + bb.w; if (t > 0.f) acc += t * ww.w;
    }
    #pragma unroll
    for (int o = 16; o; o >>= 1) acc += __shfl_xor_sync(0xffffffffu, acc, o);
    if (lane == 0) out[e] = 1.f / (1.f + __expf(-(acc + b2[0])));
}

extern "C" void kernel_launch(void* const* d_in, const int* in_sizes, int n_in,
                              void* d_out, int out_size) {
    const float* h  = (const float*)d_in[0];
    const int*   src = (const int*)d_in[1];
    const int*   dst = (const int*)d_in[2];
    const float* W1 = (const float*)d_in[3];
    const float* b1 = (const float*)d_in[4];
    const float* W2 = (const float*)d_in[5];
    const float* b2 = (const float*)d_in[6];
    float* out = (float*)d_out;

    int M = in_sizes[0] / DFEAT;   // nodes
    int E = in_sizes[1];           // edges

    prep_w<<<(DFEAT * NCOLS + 255) / 256, 256>>>(W1);
    dim3 gg(NCOLS / BN, (M + BM - 1) / BM);
    gemm_tf32<<<gg, 256>>>(h, M);
    edge_mlp<<<(E + 7) / 8, 256>>>(src, dst, b1, W2, b2, out, E);
}

// round 2
// speedup vs baseline: 1.5735x; 1.5735x over previous
#include <cuda_runtime.h>
#include <cuda_bf16.h>
#include <cstdint>

#define DFEAT 256
#define NCOLS 512
#define MAXN  100000

// Scratch: P = [u | v] per node in bf16 (100 MB -> L2-resident), Wcat fp32(tf32).
__device__ __nv_bfloat16 g_P[(size_t)MAXN * NCOLS];  // 102.4 MB
__device__ float g_W[DFEAT * NCOLS];                 // 512 KB

__device__ __forceinline__ uint32_t f2tf32(float x) {
    uint32_t r;
    asm("cvt.rna.tf32.f32 %0, %1;" : "=r"(r) : "f"(x));
    return r;
}

// Build Wcat[k][j] = W1[k][j] (j<256) | W1[256+k][j-256], tf32-rounded.
__global__ void prep_w(const float* __restrict__ W1) {
    int idx = blockIdx.x * blockDim.x + threadIdx.x;
    if (idx >= DFEAT * NCOLS) return;
    int k = idx >> 9;
    int j = idx & 511;
    float w = (j < DFEAT) ? W1[k * DFEAT + j]
                          : W1[(DFEAT + k) * DFEAT + (j - DFEAT)];
    g_W[idx] = __uint_as_float(f2tf32(w));
}

// ------------- tf32 tensor-core GEMM, cp.async 2-stage pipeline --------------
#define BM 128
#define BN 128
#define BK 32
#define ASTR 36    // pad: conflict-free A fragment LDS (36*4=144B, 16B-aligned rows)
#define BSTR 136   // pad: conflict-free B fragment LDS (544B rows)
#define A_STAGE (BM * ASTR)
#define B_STAGE (BK * BSTR)
#define SMEM_FLOATS (2 * (A_STAGE + B_STAGE))

__device__ __forceinline__ void cp16(float* dst_s, const float* src_g, bool pred) {
    uint32_t d = (uint32_t)__cvta_generic_to_shared(dst_s);
    int sz = pred ? 16 : 0;   // 0 => zero-fill
    asm volatile("cp.async.ca.shared.global [%0], [%1], 16, %2;"
                 :: "r"(d), "l"(src_g), "r"(sz));
}

__global__ __launch_bounds__(256, 1) void gemm_tf32(const float* __restrict__ h, int M) {
    extern __shared__ float smem[];
    float* As = smem;                  // [2][A_STAGE]
    float* Bs = smem + 2 * A_STAGE;    // [2][B_STAGE]

    int tid  = threadIdx.x;
    int lane = tid & 31, warp = tid >> 5;
    int wm = (warp >> 2) * 64;         // warp grid 2(m) x 4(n), warp tile 64x32
    int wn = (warp & 3) * 32;
    int g  = lane >> 2, tg = lane & 3;
    int rowBase = blockIdx.y * BM;
    int nBase   = blockIdx.x * BN;

    float c[4][4][4];
    #pragma unroll
    for (int i = 0; i < 4; i++)
        #pragma unroll
        for (int j = 0; j < 4; j++)
            #pragma unroll
            for (int q = 0; q < 4; q++) c[i][j][q] = 0.f;

    // A-load mapping: 1024 float4 slots, 4 per thread
    int ar[4], ac[4];
    #pragma unroll
    for (int i = 0; i < 4; i++) {
        int idx = tid + 256 * i;
        ar[i] = idx >> 3;           // row 0..127
        ac[i] = (idx & 7) << 2;     // col 0..28 step 4
    }
    // B-load mapping
    int br[4], bc[4];
    #pragma unroll
    for (int i = 0; i < 4; i++) {
        int idx = tid + 256 * i;
        br[i] = idx >> 5;           // row 0..31
        bc[i] = (idx & 31) << 2;    // col 0..124 step 4
    }

    auto load_stage = [&](int st, int k0) {
        float* a_s = As + st * A_STAGE;
        float* b_s = Bs + st * B_STAGE;
        #pragma unroll
        for (int i = 0; i < 4; i++) {
            int grow = rowBase + ar[i];
            cp16(a_s + ar[i] * ASTR + ac[i],
                 h + (size_t)grow * DFEAT + k0 + ac[i], grow < M);
        }
        #pragma unroll
        for (int i = 0; i < 4; i++) {
            cp16(b_s + br[i] * BSTR + bc[i],
                 g_W + (size_t)(k0 + br[i]) * NCOLS + nBase + bc[i], true);
        }
        asm volatile("cp.async.commit_group;");
    };

    load_stage(0, 0);
    int buf = 0;
    for (int k0 = 0; k0 < DFEAT; k0 += BK) {
        if (k0 + BK < DFEAT) {
            load_stage(buf ^ 1, k0 + BK);
            asm volatile("cp.async.wait_group 1;");
        } else {
            asm volatile("cp.async.wait_group 0;");
        }
        __syncthreads();

        const float* a_s = As + buf * A_STAGE;
        const float* b_s = Bs + buf * B_STAGE;
        #pragma unroll
        for (int kk = 0; kk < BK; kk += 8) {
            uint32_t a[4][4];
            #pragma unroll
            for (int mt = 0; mt < 4; mt++) {
                const float* ap = a_s + (wm + mt * 16) * ASTR + kk;
                a[mt][0] = __float_as_uint(ap[g * ASTR + tg]);
                a[mt][1] = __float_as_uint(ap[(g + 8) * ASTR + tg]);
                a[mt][2] = __float_as_uint(ap[g * ASTR + tg + 4]);
                a[mt][3] = __float_as_uint(ap[(g + 8) * ASTR + tg + 4]);
            }
            uint32_t b[4][2];
            #pragma unroll
            for (int nt = 0; nt < 4; nt++) {
                const float* bp = b_s + kk * BSTR + wn + nt * 8 + g;
                b[nt][0] = __float_as_uint(bp[tg * BSTR]);
                b[nt][1] = __float_as_uint(bp[(tg + 4) * BSTR]);
            }
            #pragma unroll
            for (int mt = 0; mt < 4; mt++)
                #pragma unroll
                for (int nt = 0; nt < 4; nt++) {
                    asm volatile(
                        "mma.sync.aligned.m16n8k8.row.col.f32.tf32.tf32.f32 "
                        "{%0,%1,%2,%3}, {%4,%5,%6,%7}, {%8,%9}, {%0,%1,%2,%3};"
                        : "+f"(c[mt][nt][0]), "+f"(c[mt][nt][1]),
                          "+f"(c[mt][nt][2]), "+f"(c[mt][nt][3])
                        : "r"(a[mt][0]), "r"(a[mt][1]), "r"(a[mt][2]), "r"(a[mt][3]),
                          "r"(b[nt][0]), "r"(b[nt][1]));
                }
        }
        __syncthreads();
        buf ^= 1;
    }

    // Epilogue -> bf16 P. C frag: c0 (g,2tg) c1 (g,2tg+1) c2 (g+8,2tg) c3 (g+8,2tg+1)
    #pragma unroll
    for (int mt = 0; mt < 4; mt++) {
        int row0 = rowBase + wm + mt * 16 + g;
        #pragma unroll
        for (int nt = 0; nt < 4; nt++) {
            int col = nBase + wn + nt * 8 + 2 * tg;
            if (row0 < M)
                *(__nv_bfloat162*)(g_P + (size_t)row0 * NCOLS + col) =
                    __float22bfloat162_rn(make_float2(c[mt][nt][0], c[mt][nt][1]));
            if (row0 + 8 < M)
                *(__nv_bfloat162*)(g_P + (size_t)(row0 + 8) * NCOLS + col) =
                    __float22bfloat162_rn(make_float2(c[mt][nt][2], c[mt][nt][3]));
        }
    }
}

// ------------- edge pass: warp/edge, bf16 gathers, 2 edges in flight ---------
__device__ __forceinline__ float edge_dot(uint4 uu, uint4 vv,
                                          const float* bb, const float* ww) {
    float acc = 0.f;
    const uint32_t* up = &uu.x;
    const uint32_t* vp = &vv.x;
    #pragma unroll
    for (int q = 0; q < 4; q++) {
        float2 uf = __bfloat1622float2(*(const __nv_bfloat162*)&up[q]);
        float2 vf = __bfloat1622float2(*(const __nv_bfloat162*)&vp[q]);
        float t;
        t = uf.x + vf.x + bb[2 * q];     if (t > 0.f) acc += t * ww[2 * q];
        t = uf.y + vf.y + bb[2 * q + 1]; if (t > 0.f) acc += t * ww[2 * q + 1];
    }
    return acc;
}

__global__ __launch_bounds__(256) void edge_mlp(
        const int* __restrict__ src, const int* __restrict__ dst,
        const float* __restrict__ b1, const float* __restrict__ W2,
        const float* __restrict__ b2, float* __restrict__ out, int E) {
    int tid = threadIdx.x;
    int lane = tid & 31;
    int gwarp = blockIdx.x * 8 + (tid >> 5);
    int nwarps = gridDim.x * 8;

    // per-lane slice j = lane*8 .. lane*8+7 held in registers
    float bb[8], ww[8];
    #pragma unroll
    for (int i = 0; i < 8; i++) {
        bb[i] = __ldg(b1 + lane * 8 + i);
        ww[i] = __ldg(W2 + lane * 8 + i);
    }
    float bias2 = __ldg(b2);

    const __nv_bfloat16* P = g_P;
    for (int e = gwarp; e < E; e += 2 * nwarps) {
        int e2 = e + nwarps;
        bool have2 = e2 < E;
        int s0 = src[e], d0 = dst[e];
        int s1 = have2 ? src[e2] : 0;
        int d1 = have2 ? dst[e2] : 0;

        uint4 u0 = *(const uint4*)(P + (size_t)s0 * NCOLS + lane * 8);
        uint4 v0 = *(const uint4*)(P + (size_t)d0 * NCOLS + DFEAT + lane * 8);
        uint4 u1 = *(const uint4*)(P + (size_t)s1 * NCOLS + lane * 8);
        uint4 v1 = *(const uint4*)(P + (size_t)d1 * NCOLS + DFEAT + lane * 8);

        float a0 = edge_dot(u0, v0, bb, ww);
        float a1 = edge_dot(u1, v1, bb, ww);
        #pragma unroll
        for (int o = 16; o; o >>= 1) {
            a0 += __shfl_xor_sync(0xffffffffu, a0, o);
            a1 += __shfl_xor_sync(0xffffffffu, a1, o);
        }
        if (lane == 0) {
            out[e] = 1.f / (1.f + __expf(-(a0 + bias2)));
            if (have2) out[e2] = 1.f / (1.f + __expf(-(a1 + bias2)));
        }
    }
}

extern "C" void kernel_launch(void* const* d_in, const int* in_sizes, int n_in,
                              void* d_out, int out_size) {
    const float* h   = (const float*)d_in[0];
    const int*   src = (const int*)d_in[1];
    const int*   dst = (const int*)d_in[2];
    const float* W1  = (const float*)d_in[3];
    const float* b1  = (const float*)d_in[4];
    const float* W2  = (const float*)d_in[5];
    const float* b2  = (const float*)d_in[6];
    float* out = (float*)d_out;

    int M = in_sizes[0] / DFEAT;
    int E = in_sizes[1];

    prep_w<<<(DFEAT * NCOLS + 255) / 256, 256>>>(W1);

    int smem_bytes = SMEM_FLOATS * (int)sizeof(float);   // ~70 KB
    cudaFuncSetAttribute(gemm_tf32, cudaFuncAttributeMaxDynamicSharedMemorySize,
                         smem_bytes);
    dim3 gg(NCOLS / BN, (M + BM - 1) / BM);
    gemm_tf32<<<gg, 256, smem_bytes>>>(h, M);

    edge_mlp<<<2368, 256>>>(src, dst, b1, W2, b2, out, E);
}